// round 17
// baseline (speedup 1.0000x reference)
#include <cuda_runtime.h>
#include <cuda_bf16.h>
#include <cuda_fp16.h>
#include <cstdint>

#define NN 100000
#define NE 800000
#define F  128
#define C  64
#define CAP 64                  // per-node bucket capacity (deg ~ Poisson(8); P(>=64) ~ 1e-40)

typedef unsigned long long ull;

// ---- device scratch (no allocations allowed) ----
__device__ uint4 g_yh[NN * 8];          // y in fp16: 64 halves = 128B/row (12.8 MB, L2-resident)
__device__ int   g_cnt[NN];             // per-node fill cursor == degree (re-zeroed in k_out)
__device__ int   g_srcs[NN * CAP];      // padded neighbor buckets (25.6 MB, only 3.2 MB touched)

__device__ __forceinline__ uint32_t h2_bits(__half2 h) {
    uint32_t u;
    __builtin_memcpy(&u, &h, 4);
    return u;
}

// ---------------- one-pass bucket fill (replaces count+scan+scatter) ----------------
__global__ void k_fill(const int* __restrict__ src,
                       const int* __restrict__ dst) {
    int e = blockIdx.x * 256 + threadIdx.x;
    if (e < NE) {
        int d = dst[e];
        int slot = atomicAdd(&g_cnt[d], 1);
        if (slot < CAP) g_srcs[(size_t)d * CAP + slot] = src[e];
    }
}

// ============ tensor-core projection: A from GLOBAL registers, B in smem ============
// Per CTA: M=128 nodes (8 warps x 16 rows), N=64 classes, K=128.
// bf16 2-term split: D = Ahi*Bhi + Alo*Bhi + Ahi*Blo  (fp32 accumulate), y stored fp16.
#define AS 136
#define ASB (AS * 2)
#define B_LO_OFF (64 * ASB)

__device__ __forceinline__ uint32_t pack_bf2(__nv_bfloat16 a, __nv_bfloat16 b) {
    return (uint32_t)__bfloat16_as_ushort(a) | ((uint32_t)__bfloat16_as_ushort(b) << 16);
}

__device__ __forceinline__ void cvt_hilo(float2 f, uint32_t& hi, uint32_t& lo) {
    __nv_bfloat16 hx = __float2bfloat16(f.x);
    __nv_bfloat16 hy = __float2bfloat16(f.y);
    __nv_bfloat16 lx = __float2bfloat16(f.x - __bfloat162float(hx));
    __nv_bfloat16 ly = __float2bfloat16(f.y - __bfloat162float(hy));
    hi = pack_bf2(hx, hy);
    lo = pack_bf2(lx, ly);
}

__device__ __forceinline__ void mma16816(float* c, const uint32_t* a,
                                         uint32_t b0, uint32_t b1) {
    asm volatile(
        "mma.sync.aligned.m16n8k16.row.col.f32.bf16.bf16.f32 "
        "{%0,%1,%2,%3}, {%4,%5,%6,%7}, {%8,%9}, {%0,%1,%2,%3};"
        : "+f"(c[0]), "+f"(c[1]), "+f"(c[2]), "+f"(c[3])
        : "r"(a[0]), "r"(a[1]), "r"(a[2]), "r"(a[3]), "r"(b0), "r"(b1));
}

__global__ void __launch_bounds__(256) k_gemm_mma(const float* __restrict__ x,
                                                  const float* __restrict__ W) {
    __shared__ char smem[2 * 64 * ASB];   // B hi at 0, B lo at B_LO_OFF
    int tid = threadIdx.x;
    int base = blockIdx.x * 128;

    for (int i = tid; i < 64 * 32; i += 256) {
        int row = i >> 5, kq = i & 31;
        float4 v = ((const float4*)W)[row * 32 + kq];
        uint32_t h0, l0, h1, l1;
        cvt_hilo(make_float2(v.x, v.y), h0, l0);
        cvt_hilo(make_float2(v.z, v.w), h1, l1);
        uint32_t off = row * ASB + kq * 8;
        *(ull*)(smem + off)            = (ull)h0 | ((ull)h1 << 32);
        *(ull*)(smem + B_LO_OFF + off) = (ull)l0 | ((ull)l1 << 32);
    }
    __syncthreads();

    int w  = tid >> 5;
    int l  = tid & 31;
    int g  = l >> 2;
    int tg = l & 3;
    int r0 = base + w * 16 + g;
    int r1 = r0 + 8;
    bool v0 = r0 < NN, v1 = r1 < NN;
    const float* xr0 = x + (size_t)r0 * F;
    const float* xr1 = x + (size_t)r1 * F;

    float c[8][4];
    #pragma unroll
    for (int nt = 0; nt < 8; nt++)
        #pragma unroll
        for (int j = 0; j < 4; j++) c[nt][j] = 0.f;

    const float2 z2 = make_float2(0.f, 0.f);
    #pragma unroll
    for (int ks = 0; ks < 8; ks++) {
        int kA = ks * 16 + tg * 2;
        float2 f0 = v0 ? *(const float2*)(xr0 + kA)     : z2;
        float2 f1 = v1 ? *(const float2*)(xr1 + kA)     : z2;
        float2 f2 = v0 ? *(const float2*)(xr0 + kA + 8) : z2;
        float2 f3 = v1 ? *(const float2*)(xr1 + kA + 8) : z2;
        uint32_t ah[4], al[4];
        cvt_hilo(f0, ah[0], al[0]);
        cvt_hilo(f1, ah[1], al[1]);
        cvt_hilo(f2, ah[2], al[2]);
        cvt_hilo(f3, ah[3], al[3]);
        #pragma unroll
        for (int nt = 0; nt < 8; nt++) {
            uint32_t boff = (nt * 8 + g) * ASB + (ks * 16 + tg * 2) * 2;
            uint32_t bh0 = *(const uint32_t*)(smem + boff);
            uint32_t bh1 = *(const uint32_t*)(smem + boff + 16);
            uint32_t bl0 = *(const uint32_t*)(smem + B_LO_OFF + boff);
            uint32_t bl1 = *(const uint32_t*)(smem + B_LO_OFF + boff + 16);
            mma16816(c[nt], ah, bh0, bh1);
            mma16816(c[nt], al, bh0, bh1);
            mma16816(c[nt], ah, bl0, bl1);
        }
    }

    // epilogue: pack fp32 accum -> fp16 pairs (u32 index k holds classes 2k,2k+1)
    uint32_t* yh = (uint32_t*)g_yh;
    #pragma unroll
    for (int nt = 0; nt < 8; nt++) {
        if (v0) yh[(size_t)r0 * 32 + nt * 4 + tg] =
            h2_bits(__floats2half2_rn(c[nt][0], c[nt][1]));
        if (v1) yh[(size_t)r1 * 32 + nt * 4 + tg] =
            h2_bits(__floats2half2_rn(c[nt][2], c[nt][3]));
    }
}

// ---------------- gather + epilogue (fp16 rows: 128B/edge, 8 lanes/node) ----------------
__global__ void __launch_bounds__(256) k_out(const float* __restrict__ bn,
                                             float* __restrict__ out) {
    int tid = threadIdx.x;
    int l  = tid & 7;                      // lane owns classes l*8 .. l*8+7
    int nl = tid >> 3;
    int v  = blockIdx.x * 32 + nl;         // 3125 * 32 == 100000

    int deg = g_cnt[v];                    // all 8 lanes read (broadcast) ...
    if (l == 0) g_cnt[v] = 0;              // ... then lane 0 restores replay invariant
    deg = deg < CAP ? deg : CAP;

    uint4 sv = g_yh[(size_t)v * 8 + l];    // self term
    float2 a0 = __half22float2(*(const __half2*)&sv.x);
    float2 a1 = __half22float2(*(const __half2*)&sv.y);
    float2 a2 = __half22float2(*(const __half2*)&sv.z);
    float2 a3 = __half22float2(*(const __half2*)&sv.w);

    const int* sl = g_srcs + (size_t)v * CAP;
    int j = 0;
    for (; j + 2 <= deg; j += 2) {
        int s0 = sl[j];
        int s1 = sl[j + 1];
        uint4 t0 = g_yh[(size_t)s0 * 8 + l];
        uint4 t1 = g_yh[(size_t)s1 * 8 + l];
        float2 p;
        p = __half22float2(*(const __half2*)&t0.x); a0.x += p.x; a0.y += p.y;
        p = __half22float2(*(const __half2*)&t0.y); a1.x += p.x; a1.y += p.y;
        p = __half22float2(*(const __half2*)&t0.z); a2.x += p.x; a2.y += p.y;
        p = __half22float2(*(const __half2*)&t0.w); a3.x += p.x; a3.y += p.y;
        p = __half22float2(*(const __half2*)&t1.x); a0.x += p.x; a0.y += p.y;
        p = __half22float2(*(const __half2*)&t1.y); a1.x += p.x; a1.y += p.y;
        p = __half22float2(*(const __half2*)&t1.z); a2.x += p.x; a2.y += p.y;
        p = __half22float2(*(const __half2*)&t1.w); a3.x += p.x; a3.y += p.y;
    }
    for (; j < deg; j++) {
        int s = sl[j];
        uint4 t = g_yh[(size_t)s * 8 + l];
        float2 p;
        p = __half22float2(*(const __half2*)&t.x); a0.x += p.x; a0.y += p.y;
        p = __half22float2(*(const __half2*)&t.y); a1.x += p.x; a1.y += p.y;
        p = __half22float2(*(const __half2*)&t.z); a2.x += p.x; a2.y += p.y;
        p = __half22float2(*(const __half2*)&t.w); a3.x += p.x; a3.y += p.y;
    }

    float sc = 1.0f / (float)(deg + 1);
    float4 b0 = ((const float4*)bn)[l * 2];
    float4 b1 = ((const float4*)bn)[l * 2 + 1];
    float4 o0, o1;
    o0.x = a0.x * sc + b0.x;
    o0.y = a0.y * sc + b0.y;
    o0.z = a1.x * sc + b0.z;
    o0.w = a1.y * sc + b0.w;
    o1.x = a2.x * sc + b1.x;
    o1.y = a2.y * sc + b1.y;
    o1.z = a3.x * sc + b1.z;
    o1.w = a3.y * sc + b1.w;
    ((float4*)out)[(size_t)v * 16 + l * 2]     = o0;
    ((float4*)out)[(size_t)v * 16 + l * 2 + 1] = o1;
}

extern "C" void kernel_launch(void* const* d_in, const int* in_sizes, int n_in,
                              void* d_out, int out_size) {
    const float* x    = (const float*)d_in[0];
    const int*   esrc = (const int*)d_in[1];
    const int*   edst = (const int*)d_in[2];
    const float* W    = (const float*)d_in[3];
    const float* bn   = (const float*)d_in[4];
    float* out = (float*)d_out;

    static cudaStream_t s1 = nullptr;
    static cudaEvent_t ev_root = nullptr, ev_gemm = nullptr;
    if (!s1) {
        cudaStreamCreateWithFlags(&s1, cudaStreamNonBlocking);
        cudaEventCreateWithFlags(&ev_root, cudaEventDisableTiming);
        cudaEventCreateWithFlags(&ev_gemm, cudaEventDisableTiming);
    }

    // fork: GEMM on side stream, bucket fill on main stream
    cudaEventRecord(ev_root, 0);
    cudaStreamWaitEvent(s1, ev_root, 0);
    k_gemm_mma<<<(NN + 127) / 128, 256, 0, s1>>>(x, W);
    cudaEventRecord(ev_gemm, s1);

    k_fill<<<(NE + 255) / 256, 256>>>(esrc, edst);

    // join: k_out needs both g_yh (gemm) and buckets
    cudaStreamWaitEvent(0, ev_gemm, 0);
    k_out<<<NN / 32, 256>>>(bn, out);
}